// round 1
// baseline (speedup 1.0000x reference)
#include <cuda_runtime.h>
#include <stdint.h>

// 12-bit ripple-borrow subtractor on binary (0/1) float spikes.
// On {0,1} inputs the soft-gate algebra equals exact boolean logic, so:
//   diffs = bits of ((a - b) mod 4096), MSB at index 0
//   borrow_out = (a < b)
// Output layout (tuple flattened): [B*12] diffs row-major, then [B] borrow.

__global__ void __launch_bounds__(256) sub12_kernel(
    const float4* __restrict__ A4,   // [B*3] float4 == [B,12] float
    const float4* __restrict__ B4,
    float4* __restrict__ D4,         // [B*3] float4 == [B,12] float diffs
    float* __restrict__ Borrow,      // [B]
    int batch)
{
    int i = blockIdx.x * blockDim.x + threadIdx.x;
    if (i >= batch) return;

    const float4 a0 = A4[i * 3 + 0];
    const float4 a1 = A4[i * 3 + 1];
    const float4 a2 = A4[i * 3 + 2];
    const float4 b0 = B4[i * 3 + 0];
    const float4 b1 = B4[i * 3 + 1];
    const float4 b2 = B4[i * 3 + 2];

    // Pack bits: index 0 = MSB ... index 11 = LSB.
    uint32_t ia = 0, ib = 0;
    {
        const float av[12] = {a0.x, a0.y, a0.z, a0.w,
                              a1.x, a1.y, a1.z, a1.w,
                              a2.x, a2.y, a2.z, a2.w};
        const float bv[12] = {b0.x, b0.y, b0.z, b0.w,
                              b1.x, b1.y, b1.z, b1.w,
                              b2.x, b2.y, b2.z, b2.w};
#pragma unroll
        for (int k = 0; k < 12; k++) {
            ia |= (av[k] != 0.0f ? 1u : 0u) << (11 - k);
            ib |= (bv[k] != 0.0f ? 1u : 0u) << (11 - k);
        }
    }

    const uint32_t diff = (ia - ib) & 0xFFFu;
    const float borrow_out = (ia < ib) ? 1.0f : 0.0f;

    float dv[12];
#pragma unroll
    for (int k = 0; k < 12; k++)
        dv[k] = ((diff >> (11 - k)) & 1u) ? 1.0f : 0.0f;

    D4[i * 3 + 0] = make_float4(dv[0], dv[1], dv[2], dv[3]);
    D4[i * 3 + 1] = make_float4(dv[4], dv[5], dv[6], dv[7]);
    D4[i * 3 + 2] = make_float4(dv[8], dv[9], dv[10], dv[11]);
    Borrow[i] = borrow_out;
}

extern "C" void kernel_launch(void* const* d_in, const int* in_sizes, int n_in,
                              void* d_out, int out_size)
{
    const float4* A4 = (const float4*)d_in[0];
    const float4* B4 = (const float4*)d_in[1];
    const int batch = in_sizes[0] / 12;

    float* out = (float*)d_out;
    float4* D4 = (float4*)out;            // first B*12 floats (48B rows, f4-aligned)
    float* Borrow = out + (size_t)batch * 12;  // last B floats

    const int threads = 256;
    const int blocks = (batch + threads - 1) / threads;
    sub12_kernel<<<blocks, threads>>>(A4, B4, D4, Borrow, batch);
}